// round 2
// baseline (speedup 1.0000x reference)
#include <cuda_runtime.h>
#include <cuda_bf16.h>
#include <math.h>

// Problem constants
#define B_SZ   4
#define SEQ    2048
#define DMODEL 1024
#define NSTATE 16
#define MROWS  (B_SZ*SEQ)        // 8192
#define NCHUNK 32
#define CLEN   64                // NCHUNK*CLEN == SEQ

// ---------------- device scratch (no allocations allowed) ----------------
// All arrays 16B-aligned: they are accessed through float4* casts.
__device__ __align__(16) float g_delta[MROWS*DMODEL];           // softplus(x@Wd+bd)   32 MB
__device__ __align__(16) float g_Bm[MROWS*NSTATE];              // x@Wb+bb
__device__ __align__(16) float g_Cm[MROWS*NSTATE];              // x@Wc+bc
__device__ __align__(16) float g_A2[DMODEL*NSTATE];             // -exp(A_log)*log2(e)
__device__ __align__(16) float g_P [B_SZ*NCHUNK*DMODEL*NSTATE]; // per-chunk prod(a)   8 MB
__device__ __align__(16) float g_E [B_SZ*NCHUNK*DMODEL*NSTATE]; // per-chunk endpoint  8 MB
__device__ __align__(16) float g_hin[B_SZ*NCHUNK*DMODEL*NSTATE];// incoming state      8 MB

// ---------------- helpers ----------------
__device__ __forceinline__ float ex2(float x) {
    float r;
    asm("ex2.approx.ftz.f32 %0, %1;" : "=f"(r) : "f"(x));
    return r;
}
__device__ __forceinline__ float softplus_f(float z) {
    return fmaxf(z, 0.0f) + log1pf(__expf(-fabsf(z)));
}

// ---------------- kernel 0: A2 = -exp(A_log) * log2(e) ----------------
__global__ void prep_A2_kernel(const float* __restrict__ A_log) {
    int i = blockIdx.x * 256 + threadIdx.x;
    if (i < DMODEL*NSTATE)
        g_A2[i] = -__expf(A_log[i]) * 1.44269504088896f;
}

// ---------------- kernel 1: delta = softplus(x @ Wd + bd) ----------------
// FP32 SGEMM, 128x128x8 tile, 256 threads, 8x8 microtile, double-buffered smem
#define BM 128
#define BN 128
#define BK 8
#define SPAD 132   // padded row stride (floats)

__global__ __launch_bounds__(256) void gemm_softplus_kernel(
    const float* __restrict__ X, const float* __restrict__ W,
    const float* __restrict__ bias)
{
    const int K = DMODEL, N = DMODEL;
    __shared__ __align__(16) float As[2][BK][SPAD];
    __shared__ __align__(16) float Bs[2][BK][SPAD];

    int tid  = threadIdx.x;
    int brow = blockIdx.y * BM;
    int bcol = blockIdx.x * BN;

    int ar = tid >> 1;            // 0..127
    int ac = (tid & 1) * 4;       // 0 or 4
    int br = tid >> 5;            // 0..7
    int bc = (tid & 31) * 4;      // 0..124

    const float* Aptr = X + (size_t)(brow + ar) * K + ac;
    const float* Bptr = W + (size_t)br * N + bcol + bc;

    // preload tile 0
    float4 a0 = *(const float4*)Aptr;
    float4 b0 = *(const float4*)Bptr;
    {
        float av[4] = {a0.x, a0.y, a0.z, a0.w};
        #pragma unroll
        for (int j = 0; j < 4; j++) As[0][ac + j][ar] = av[j];
        *(float4*)&Bs[0][br][bc] = b0;
    }
    __syncthreads();

    int trow = (tid >> 4) * 8;
    int tcol = (tid & 15) * 8;

    float acc[8][8];
    #pragma unroll
    for (int i = 0; i < 8; i++)
        #pragma unroll
        for (int j = 0; j < 8; j++) acc[i][j] = 0.0f;

    int buf = 0;
    for (int kt = BK; kt <= K; kt += BK) {
        float4 a1, b1;
        bool pref = (kt < K);
        if (pref) {
            a1 = *(const float4*)(Aptr + kt);
            b1 = *(const float4*)(Bptr + (size_t)kt * N);
        }
        #pragma unroll
        for (int k = 0; k < BK; k++) {
            float ra[8], rb[8];
            *(float4*)&ra[0] = *(const float4*)&As[buf][k][trow];
            *(float4*)&ra[4] = *(const float4*)&As[buf][k][trow + 4];
            *(float4*)&rb[0] = *(const float4*)&Bs[buf][k][tcol];
            *(float4*)&rb[4] = *(const float4*)&Bs[buf][k][tcol + 4];
            #pragma unroll
            for (int i = 0; i < 8; i++)
                #pragma unroll
                for (int j = 0; j < 8; j++)
                    acc[i][j] = fmaf(ra[i], rb[j], acc[i][j]);
        }
        if (pref) {
            int nb = buf ^ 1;
            float av[4] = {a1.x, a1.y, a1.z, a1.w};
            #pragma unroll
            for (int j = 0; j < 4; j++) As[nb][ac + j][ar] = av[j];
            *(float4*)&Bs[nb][br][bc] = b1;
            __syncthreads();
            buf = nb;
        }
    }

    // epilogue: + bias, softplus, store
    float bv[8];
    *(float4*)&bv[0] = *(const float4*)(bias + bcol + tcol);
    *(float4*)&bv[4] = *(const float4*)(bias + bcol + tcol + 4);
    #pragma unroll
    for (int i = 0; i < 8; i++) {
        int row = brow + trow + i;
        float* orow = g_delta + (size_t)row * N + bcol + tcol;
        float o[8];
        #pragma unroll
        for (int j = 0; j < 8; j++) o[j] = softplus_f(acc[i][j] + bv[j]);
        *(float4*)orow       = *(float4*)&o[0];
        *(float4*)(orow + 4) = *(float4*)&o[4];
    }
}

// ---------------- kernel 2: Bm = x@Wb+bb, Cm = x@Wc+bc ----------------
// 8 warps/block, warp-per-row, lane = output column (0..15 -> B, 16..31 -> C)
__global__ __launch_bounds__(256) void bc_kernel(
    const float* __restrict__ X,
    const float* __restrict__ Wb, const float* __restrict__ bbv,
    const float* __restrict__ Wc, const float* __restrict__ bcv)
{
    __shared__ __align__(16) float Ws[128][32];
    __shared__ __align__(16) float Xs[8][128];
    int tid  = threadIdx.x;
    int lane = tid & 31;
    int warp = tid >> 5;
    int row0 = blockIdx.x * 8;

    float acc = 0.0f;
    for (int kt = 0; kt < DMODEL; kt += 128) {
        __syncthreads();
        {
            int r  = tid >> 1;       // 0..127
            int hs = tid & 1;        // 0 -> Wb cols 0..15 ; 1 -> Wc cols 16..31
            const float* src = (hs ? Wc : Wb) + (size_t)(kt + r) * NSTATE;
            float4 v0 = ((const float4*)src)[0];
            float4 v1 = ((const float4*)src)[1];
            float4 v2 = ((const float4*)src)[2];
            float4 v3 = ((const float4*)src)[3];
            int cb = hs * 16;
            *(float4*)&Ws[r][cb + 0]  = v0;
            *(float4*)&Ws[r][cb + 4]  = v1;
            *(float4*)&Ws[r][cb + 8]  = v2;
            *(float4*)&Ws[r][cb + 12] = v3;
        }
        {
            int rr = tid >> 5;
            int cc = (tid & 31) * 4;
            *(float4*)&Xs[rr][cc] =
                *(const float4*)(X + (size_t)(row0 + rr) * DMODEL + kt + cc);
        }
        __syncthreads();
        #pragma unroll 8
        for (int kk = 0; kk < 128; kk++)
            acc = fmaf(Xs[warp][kk], Ws[kk][lane], acc);
    }
    acc += (lane < NSTATE) ? bbv[lane] : bcv[lane - NSTATE];
    int row = row0 + warp;
    if (lane < NSTATE) g_Bm[row * NSTATE + lane] = acc;
    else               g_Cm[row * NSTATE + lane - NSTATE] = acc;
}

// ---------------- kernel 3: scan phase A (per-chunk P, E with h_in = 0) ----
__global__ __launch_bounds__(256) void scan_phaseA(const float* __restrict__ X)
{
    int tid = threadIdx.x;
    int d   = blockIdx.x * 256 + tid;
    int c   = blockIdx.y;
    int b   = blockIdx.z;

    __shared__ __align__(16) float Bsm[CLEN][NSTATE];
    {
        const float4* src = (const float4*)(g_Bm + (size_t)(b * SEQ + c * CLEN) * NSTATE);
        ((float4*)Bsm)[tid] = src[tid];   // 256 float4 = 64*16 floats
    }
    float A2r[16];
    {
        const float4* ap = (const float4*)(g_A2 + (size_t)d * NSTATE);
        *(float4*)&A2r[0]  = ap[0];
        *(float4*)&A2r[4]  = ap[1];
        *(float4*)&A2r[8]  = ap[2];
        *(float4*)&A2r[12] = ap[3];
    }
    __syncthreads();

    float P[16], E[16];
    #pragma unroll
    for (int n = 0; n < 16; n++) { P[n] = 1.0f; E[n] = 0.0f; }

    size_t xoff = (size_t)(b * SEQ + c * CLEN) * DMODEL + d;
    const float* xp = X + xoff;
    const float* dp = g_delta + xoff;

    #pragma unroll 2
    for (int t = 0; t < CLEN; t++) {
        float xv = xp[(size_t)t * DMODEL];
        float dt = dp[(size_t)t * DMODEL];
        float dx = dt * xv;
        float bl[16];
        const float4* bp = (const float4*)Bsm[t];
        *(float4*)&bl[0]  = bp[0];
        *(float4*)&bl[4]  = bp[1];
        *(float4*)&bl[8]  = bp[2];
        *(float4*)&bl[12] = bp[3];
        #pragma unroll
        for (int n = 0; n < 16; n++) {
            float a = ex2(dt * A2r[n]);
            P[n] *= a;
            E[n] = fmaf(a, E[n], dx * bl[n]);
        }
    }

    size_t off = ((size_t)((b * NCHUNK + c) * DMODEL + d)) * NSTATE;
    float4* Pp = (float4*)(g_P + off);
    float4* Ep = (float4*)(g_E + off);
    Pp[0] = *(float4*)&P[0];  Pp[1] = *(float4*)&P[4];
    Pp[2] = *(float4*)&P[8];  Pp[3] = *(float4*)&P[12];
    Ep[0] = *(float4*)&E[0];  Ep[1] = *(float4*)&E[4];
    Ep[2] = *(float4*)&E[8];  Ep[3] = *(float4*)&E[12];
}

// ---------------- kernel 4: scan phase B (combine chunks sequentially) ------
__global__ __launch_bounds__(256) void scan_phaseB()
{
    int idx = blockIdx.x * 256 + threadIdx.x;       // 0..65535 = b*D*N + d*N + n
    int b   = idx >> 14;
    int rem = idx & 16383;
    size_t base = (size_t)b * NCHUNK * DMODEL * NSTATE + rem;
    float h = 0.0f;
    #pragma unroll
    for (int c = 0; c < NCHUNK; c++) {
        size_t off = base + (size_t)c * (DMODEL * NSTATE);
        g_hin[off] = h;
        h = fmaf(g_P[off], h, g_E[off]);
    }
}

// ---------------- kernel 5: scan phase C (replay with correct h_in, emit y) -
__global__ __launch_bounds__(256) void scan_phaseC(
    const float* __restrict__ X, const float* __restrict__ Dskip,
    float* __restrict__ Y)
{
    int tid = threadIdx.x;
    int d   = blockIdx.x * 256 + tid;
    int c   = blockIdx.y;
    int b   = blockIdx.z;

    __shared__ __align__(16) float Bsm[CLEN][NSTATE];
    __shared__ __align__(16) float Csm[CLEN][NSTATE];
    {
        size_t so = (size_t)(b * SEQ + c * CLEN) * NSTATE;
        ((float4*)Bsm)[tid] = ((const float4*)(g_Bm + so))[tid];
        ((float4*)Csm)[tid] = ((const float4*)(g_Cm + so))[tid];
    }
    float A2r[16];
    {
        const float4* ap = (const float4*)(g_A2 + (size_t)d * NSTATE);
        *(float4*)&A2r[0]  = ap[0];
        *(float4*)&A2r[4]  = ap[1];
        *(float4*)&A2r[8]  = ap[2];
        *(float4*)&A2r[12] = ap[3];
    }
    float h[16];
    {
        size_t off = ((size_t)((b * NCHUNK + c) * DMODEL + d)) * NSTATE;
        const float4* hp = (const float4*)(g_hin + off);
        *(float4*)&h[0]  = hp[0];
        *(float4*)&h[4]  = hp[1];
        *(float4*)&h[8]  = hp[2];
        *(float4*)&h[12] = hp[3];
    }
    float dsk = Dskip[d];
    __syncthreads();

    size_t xoff = (size_t)(b * SEQ + c * CLEN) * DMODEL + d;
    const float* xp = X + xoff;
    const float* dp = g_delta + xoff;
    float* yp = Y + xoff;

    #pragma unroll 2
    for (int t = 0; t < CLEN; t++) {
        float xv = xp[(size_t)t * DMODEL];
        float dt = dp[(size_t)t * DMODEL];
        float dx = dt * xv;
        float bl[16], cl[16];
        const float4* bp = (const float4*)Bsm[t];
        const float4* cp = (const float4*)Csm[t];
        *(float4*)&bl[0]  = bp[0]; *(float4*)&bl[4]  = bp[1];
        *(float4*)&bl[8]  = bp[2]; *(float4*)&bl[12] = bp[3];
        *(float4*)&cl[0]  = cp[0]; *(float4*)&cl[4]  = cp[1];
        *(float4*)&cl[8]  = cp[2]; *(float4*)&cl[12] = cp[3];
        float acc0 = 0.0f, acc1 = 0.0f;
        #pragma unroll
        for (int n = 0; n < 16; n += 2) {
            float a0 = ex2(dt * A2r[n]);
            float a1 = ex2(dt * A2r[n + 1]);
            h[n]     = fmaf(a0, h[n],     dx * bl[n]);
            h[n + 1] = fmaf(a1, h[n + 1], dx * bl[n + 1]);
            acc0 = fmaf(h[n],     cl[n],     acc0);
            acc1 = fmaf(h[n + 1], cl[n + 1], acc1);
        }
        yp[(size_t)t * DMODEL] = acc0 + acc1 + xv * dsk;
    }
}

// ---------------- launch ----------------
extern "C" void kernel_launch(void* const* d_in, const int* in_sizes, int n_in,
                              void* d_out, int out_size)
{
    const float* x     = (const float*)d_in[0];
    const float* A_log = (const float*)d_in[1];
    const float* Dsk   = (const float*)d_in[2];
    const float* Wd    = (const float*)d_in[3];
    const float* bd    = (const float*)d_in[4];
    const float* Wb    = (const float*)d_in[5];
    const float* bb    = (const float*)d_in[6];
    const float* Wc    = (const float*)d_in[7];
    const float* bc    = (const float*)d_in[8];
    float* y = (float*)d_out;

    prep_A2_kernel<<<(DMODEL*NSTATE + 255) / 256, 256>>>(A_log);
    gemm_softplus_kernel<<<dim3(DMODEL / BN, MROWS / BM), 256>>>(x, Wd, bd);
    bc_kernel<<<MROWS / 8, 256>>>(x, Wb, bb, Wc, bc);
    scan_phaseA<<<dim3(DMODEL / 256, NCHUNK, B_SZ), 256>>>(x);
    scan_phaseB<<<(B_SZ * DMODEL * NSTATE) / 256, 256>>>();
    scan_phaseC<<<dim3(DMODEL / 256, NCHUNK, B_SZ), 256>>>(x, Dsk, y);
}

// round 3
// speedup vs baseline: 1.6883x; 1.6883x over previous
#include <cuda_runtime.h>
#include <cuda_bf16.h>
#include <math.h>
#include <stdint.h>

// Problem constants
#define B_SZ   4
#define SEQ    2048
#define DMODEL 1024
#define NSTATE 16
#define MROWS  (B_SZ*SEQ)        // 8192
#define NCHUNK 32
#define CLEN   64                // NCHUNK*CLEN == SEQ

// ---------------- device scratch (no allocations allowed) ----------------
__device__ __align__(16) float g_delta[MROWS*DMODEL];           // softplus(x@Wd+bd)   32 MB
__device__ __align__(16) float g_Bm[MROWS*NSTATE];              // x@Wb+bb
__device__ __align__(16) float g_Cm[MROWS*NSTATE];              // x@Wc+bc
__device__ __align__(16) float g_A2[DMODEL*NSTATE];             // -exp(A_log)*log2(e)
__device__ __align__(16) float g_P [B_SZ*NCHUNK*DMODEL*NSTATE]; // per-chunk prod(a)   8 MB
__device__ __align__(16) float g_E [B_SZ*NCHUNK*DMODEL*NSTATE]; // per-chunk endpoint  8 MB
__device__ __align__(16) float g_hin[B_SZ*NCHUNK*DMODEL*NSTATE];// incoming state      8 MB

// ---------------- helpers ----------------
__device__ __forceinline__ float ex2(float x) {
    float r;
    asm("ex2.approx.ftz.f32 %0, %1;" : "=f"(r) : "f"(x));
    return r;
}
__device__ __forceinline__ float softplus_f(float z) {
    return fmaxf(z, 0.0f) + log1pf(__expf(-fabsf(z)));
}
__device__ __forceinline__ uint32_t to_tf32(float x) {
    uint32_t u;
    asm("cvt.rna.tf32.f32 %0, %1;" : "=r"(u) : "f"(x));
    return u;
}
__device__ __forceinline__ void mma_tf32(
    float& d0, float& d1, float& d2, float& d3,
    uint32_t a0, uint32_t a1, uint32_t a2, uint32_t a3,
    uint32_t b0, uint32_t b1)
{
    asm volatile(
        "mma.sync.aligned.m16n8k8.row.col.f32.tf32.tf32.f32 "
        "{%0,%1,%2,%3}, {%4,%5,%6,%7}, {%8,%9}, {%0,%1,%2,%3};"
        : "+f"(d0), "+f"(d1), "+f"(d2), "+f"(d3)
        : "r"(a0), "r"(a1), "r"(a2), "r"(a3), "r"(b0), "r"(b1));
}

// ---------------- kernel 0: A2 = -exp(A_log) * log2(e) ----------------
__global__ void prep_A2_kernel(const float* __restrict__ A_log) {
    int i = blockIdx.x * 256 + threadIdx.x;
    if (i < DMODEL*NSTATE)
        g_A2[i] = -__expf(A_log[i]) * 1.44269504088896f;
}

// ---------------- kernel 1: delta = softplus(x @ Wd + bd), tf32 tensor-core
// 128x128x16 block tile, 256 threads (8 warps), warp tile 64x32 via m16n8k8.
// Smem stores tf32 bit patterns; 136-float row pad -> conflict-free frag reads.
#define TBM 128
#define TBN 128
#define TBK 16
#define TPAD 136

__global__ __launch_bounds__(256) void gemm_tf32_softplus(
    const float* __restrict__ X, const float* __restrict__ W,
    const float* __restrict__ bias)
{
    const int K = DMODEL, N = DMODEL;
    __shared__ __align__(16) uint32_t As[2][TBK][TPAD];   // [k][m]
    __shared__ __align__(16) uint32_t Bs[2][TBK][TPAD];   // [k][n]

    int tid  = threadIdx.x;
    int brow = blockIdx.y * TBM;
    int bcol = blockIdx.x * TBN;

    // global load mapping
    // A tile: 128 rows x 16 k = 512 float4; thread handles f = tid, tid+256
    //   m = f>>2, kq = (f&3)*4
    // B tile: 16 k x 128 n = 512 float4; k = f>>5, nq = (f&31)*4
    int am0 = tid >> 2,        akq = (tid & 3) * 4;
    int am1 = (tid + 256) >> 2;                       // akq same (tid&3 periodic)
    int bk0 = tid >> 5,        bnq = (tid & 31) * 4;
    int bk1 = (tid + 256) >> 5;

    const float* Ap0 = X + (size_t)(brow + am0) * K + akq;
    const float* Ap1 = X + (size_t)(brow + am1) * K + akq;
    const float* Bp0 = W + (size_t)bk0 * N + bcol + bnq;
    const float* Bp1 = W + (size_t)bk1 * N + bcol + bnq;

    // preload tile 0
    {
        float4 a0 = *(const float4*)Ap0;
        float4 a1 = *(const float4*)Ap1;
        float4 b0 = *(const float4*)Bp0;
        float4 b1 = *(const float4*)Bp1;
        As[0][akq+0][am0] = to_tf32(a0.x);
        As[0][akq+1][am0] = to_tf32(a0.y);
        As[0][akq+2][am0] = to_tf32(a0.z);
        As[0][akq+3][am0] = to_tf32(a0.w);
        As[0][akq+0][am1] = to_tf32(a1.x);
        As[0][akq+1][am1] = to_tf32(a1.y);
        As[0][akq+2][am1] = to_tf32(a1.z);
        As[0][akq+3][am1] = to_tf32(a1.w);
        Bs[0][bk0][bnq+0] = to_tf32(b0.x);
        Bs[0][bk0][bnq+1] = to_tf32(b0.y);
        Bs[0][bk0][bnq+2] = to_tf32(b0.z);
        Bs[0][bk0][bnq+3] = to_tf32(b0.w);
        Bs[0][bk1][bnq+0] = to_tf32(b1.x);
        Bs[0][bk1][bnq+1] = to_tf32(b1.y);
        Bs[0][bk1][bnq+2] = to_tf32(b1.z);
        Bs[0][bk1][bnq+3] = to_tf32(b1.w);
    }
    __syncthreads();

    int wid  = tid >> 5, lane = tid & 31;
    int wm   = (wid & 1) * 64;        // warp row offset within block
    int wn   = (wid >> 1) * 32;       // warp col offset within block
    int g    = lane >> 2;             // groupID 0..7
    int tg   = lane & 3;              // thread-in-group 0..3

    float acc[4][4][4];
    #pragma unroll
    for (int mf = 0; mf < 4; mf++)
        #pragma unroll
        for (int nf = 0; nf < 4; nf++)
            #pragma unroll
            for (int r = 0; r < 4; r++) acc[mf][nf][r] = 0.0f;

    int buf = 0;
    for (int kt = TBK; kt <= K; kt += TBK) {
        float4 pa0, pa1, pb0, pb1;
        bool pref = (kt < K);
        if (pref) {
            pa0 = *(const float4*)(Ap0 + kt);
            pa1 = *(const float4*)(Ap1 + kt);
            pb0 = *(const float4*)(Bp0 + (size_t)kt * N);
            pb1 = *(const float4*)(Bp1 + (size_t)kt * N);
        }

        #pragma unroll
        for (int ks = 0; ks < 2; ks++) {
            int k0 = ks * 8;
            uint32_t af[4][4], bf[4][2];
            #pragma unroll
            for (int mf = 0; mf < 4; mf++) {
                int m0 = wm + mf * 16;
                af[mf][0] = As[buf][k0+tg  ][m0+g  ];
                af[mf][1] = As[buf][k0+tg  ][m0+g+8];
                af[mf][2] = As[buf][k0+tg+4][m0+g  ];
                af[mf][3] = As[buf][k0+tg+4][m0+g+8];
            }
            #pragma unroll
            for (int nf = 0; nf < 4; nf++) {
                int n0 = wn + nf * 8;
                bf[nf][0] = Bs[buf][k0+tg  ][n0+g];
                bf[nf][1] = Bs[buf][k0+tg+4][n0+g];
            }
            #pragma unroll
            for (int mf = 0; mf < 4; mf++)
                #pragma unroll
                for (int nf = 0; nf < 4; nf++)
                    mma_tf32(acc[mf][nf][0], acc[mf][nf][1],
                             acc[mf][nf][2], acc[mf][nf][3],
                             af[mf][0], af[mf][1], af[mf][2], af[mf][3],
                             bf[nf][0], bf[nf][1]);
        }

        if (pref) {
            int nb = buf ^ 1;
            As[nb][akq+0][am0] = to_tf32(pa0.x);
            As[nb][akq+1][am0] = to_tf32(pa0.y);
            As[nb][akq+2][am0] = to_tf32(pa0.z);
            As[nb][akq+3][am0] = to_tf32(pa0.w);
            As[nb][akq+0][am1] = to_tf32(pa1.x);
            As[nb][akq+1][am1] = to_tf32(pa1.y);
            As[nb][akq+2][am1] = to_tf32(pa1.z);
            As[nb][akq+3][am1] = to_tf32(pa1.w);
            Bs[nb][bk0][bnq+0] = to_tf32(pb0.x);
            Bs[nb][bk0][bnq+1] = to_tf32(pb0.y);
            Bs[nb][bk0][bnq+2] = to_tf32(pb0.z);
            Bs[nb][bk0][bnq+3] = to_tf32(pb0.w);
            Bs[nb][bk1][bnq+0] = to_tf32(pb1.x);
            Bs[nb][bk1][bnq+1] = to_tf32(pb1.y);
            Bs[nb][bk1][bnq+2] = to_tf32(pb1.z);
            Bs[nb][bk1][bnq+3] = to_tf32(pb1.w);
            __syncthreads();
            buf = nb;
        }
    }

    // epilogue: + bias, softplus, store (c0,c1) and (c2,c3) as float2
    #pragma unroll
    for (int nf = 0; nf < 4; nf++) {
        int col = bcol + wn + nf * 8 + tg * 2;
        float bv0 = bias[col], bv1 = bias[col + 1];
        #pragma unroll
        for (int mf = 0; mf < 4; mf++) {
            int row0 = brow + wm + mf * 16 + g;
            float2 o0, o1;
            o0.x = softplus_f(acc[mf][nf][0] + bv0);
            o0.y = softplus_f(acc[mf][nf][1] + bv1);
            o1.x = softplus_f(acc[mf][nf][2] + bv0);
            o1.y = softplus_f(acc[mf][nf][3] + bv1);
            *(float2*)&g_delta[(size_t)row0 * N + col]       = o0;
            *(float2*)&g_delta[(size_t)(row0 + 8) * N + col] = o1;
        }
    }
}

// ---------------- kernel 2: Bm = x@Wb+bb, Cm = x@Wc+bc ----------------
__global__ __launch_bounds__(256) void bc_kernel(
    const float* __restrict__ X,
    const float* __restrict__ Wb, const float* __restrict__ bbv,
    const float* __restrict__ Wc, const float* __restrict__ bcv)
{
    __shared__ __align__(16) float Ws[128][32];
    __shared__ __align__(16) float Xs[8][128];
    int tid  = threadIdx.x;
    int lane = tid & 31;
    int warp = tid >> 5;
    int row0 = blockIdx.x * 8;

    float acc = 0.0f;
    for (int kt = 0; kt < DMODEL; kt += 128) {
        __syncthreads();
        {
            int r  = tid >> 1;
            int hs = tid & 1;
            const float* src = (hs ? Wc : Wb) + (size_t)(kt + r) * NSTATE;
            float4 v0 = ((const float4*)src)[0];
            float4 v1 = ((const float4*)src)[1];
            float4 v2 = ((const float4*)src)[2];
            float4 v3 = ((const float4*)src)[3];
            int cb = hs * 16;
            *(float4*)&Ws[r][cb + 0]  = v0;
            *(float4*)&Ws[r][cb + 4]  = v1;
            *(float4*)&Ws[r][cb + 8]  = v2;
            *(float4*)&Ws[r][cb + 12] = v3;
        }
        {
            int rr = tid >> 5;
            int cc = (tid & 31) * 4;
            *(float4*)&Xs[rr][cc] =
                *(const float4*)(X + (size_t)(row0 + rr) * DMODEL + kt + cc);
        }
        __syncthreads();
        #pragma unroll 8
        for (int kk = 0; kk < 128; kk++)
            acc = fmaf(Xs[warp][kk], Ws[kk][lane], acc);
    }
    acc += (lane < NSTATE) ? bbv[lane] : bcv[lane - NSTATE];
    int row = row0 + warp;
    if (lane < NSTATE) g_Bm[row * NSTATE + lane] = acc;
    else               g_Cm[row * NSTATE + lane - NSTATE] = acc;
}

// ---------------- kernel 3: scan phase A (per-chunk P, E with h_in = 0) ----
__global__ __launch_bounds__(256) void scan_phaseA(const float* __restrict__ X)
{
    int tid = threadIdx.x;
    int d   = blockIdx.x * 256 + tid;
    int c   = blockIdx.y;
    int b   = blockIdx.z;

    __shared__ __align__(16) float Bsm[CLEN][NSTATE];
    {
        const float4* src = (const float4*)(g_Bm + (size_t)(b * SEQ + c * CLEN) * NSTATE);
        ((float4*)Bsm)[tid] = src[tid];
    }
    float A2r[16];
    {
        const float4* ap = (const float4*)(g_A2 + (size_t)d * NSTATE);
        *(float4*)&A2r[0]  = ap[0];
        *(float4*)&A2r[4]  = ap[1];
        *(float4*)&A2r[8]  = ap[2];
        *(float4*)&A2r[12] = ap[3];
    }
    __syncthreads();

    float P[16], E[16];
    #pragma unroll
    for (int n = 0; n < 16; n++) { P[n] = 1.0f; E[n] = 0.0f; }

    size_t xoff = (size_t)(b * SEQ + c * CLEN) * DMODEL + d;
    const float* xp = X + xoff;
    const float* dp = g_delta + xoff;

    #pragma unroll 2
    for (int t = 0; t < CLEN; t++) {
        float xv = xp[(size_t)t * DMODEL];
        float dt = dp[(size_t)t * DMODEL];
        float dx = dt * xv;
        float bl[16];
        const float4* bp = (const float4*)Bsm[t];
        *(float4*)&bl[0]  = bp[0];
        *(float4*)&bl[4]  = bp[1];
        *(float4*)&bl[8]  = bp[2];
        *(float4*)&bl[12] = bp[3];
        #pragma unroll
        for (int n = 0; n < 16; n++) {
            float a = ex2(dt * A2r[n]);
            P[n] *= a;
            E[n] = fmaf(a, E[n], dx * bl[n]);
        }
    }

    size_t off = ((size_t)((b * NCHUNK + c) * DMODEL + d)) * NSTATE;
    float4* Pp = (float4*)(g_P + off);
    float4* Ep = (float4*)(g_E + off);
    Pp[0] = *(float4*)&P[0];  Pp[1] = *(float4*)&P[4];
    Pp[2] = *(float4*)&P[8];  Pp[3] = *(float4*)&P[12];
    Ep[0] = *(float4*)&E[0];  Ep[1] = *(float4*)&E[4];
    Ep[2] = *(float4*)&E[8];  Ep[3] = *(float4*)&E[12];
}

// ---------------- kernel 4: scan phase B (combine chunks sequentially) ------
__global__ __launch_bounds__(256) void scan_phaseB()
{
    int idx = blockIdx.x * 256 + threadIdx.x;
    int b   = idx >> 14;
    int rem = idx & 16383;
    size_t base = (size_t)b * NCHUNK * DMODEL * NSTATE + rem;
    float h = 0.0f;
    #pragma unroll
    for (int c = 0; c < NCHUNK; c++) {
        size_t off = base + (size_t)c * (DMODEL * NSTATE);
        g_hin[off] = h;
        h = fmaf(g_P[off], h, g_E[off]);
    }
}

// ---------------- kernel 5: scan phase C (replay with correct h_in, emit y) -
__global__ __launch_bounds__(256) void scan_phaseC(
    const float* __restrict__ X, const float* __restrict__ Dskip,
    float* __restrict__ Y)
{
    int tid = threadIdx.x;
    int d   = blockIdx.x * 256 + tid;
    int c   = blockIdx.y;
    int b   = blockIdx.z;

    __shared__ __align__(16) float Bsm[CLEN][NSTATE];
    __shared__ __align__(16) float Csm[CLEN][NSTATE];
    {
        size_t so = (size_t)(b * SEQ + c * CLEN) * NSTATE;
        ((float4*)Bsm)[tid] = ((const float4*)(g_Bm + so))[tid];
        ((float4*)Csm)[tid] = ((const float4*)(g_Cm + so))[tid];
    }
    float A2r[16];
    {
        const float4* ap = (const float4*)(g_A2 + (size_t)d * NSTATE);
        *(float4*)&A2r[0]  = ap[0];
        *(float4*)&A2r[4]  = ap[1];
        *(float4*)&A2r[8]  = ap[2];
        *(float4*)&A2r[12] = ap[3];
    }
    float h[16];
    {
        size_t off = ((size_t)((b * NCHUNK + c) * DMODEL + d)) * NSTATE;
        const float4* hp = (const float4*)(g_hin + off);
        *(float4*)&h[0]  = hp[0];
        *(float4*)&h[4]  = hp[1];
        *(float4*)&h[8]  = hp[2];
        *(float4*)&h[12] = hp[3];
    }
    float dsk = Dskip[d];
    __syncthreads();

    size_t xoff = (size_t)(b * SEQ + c * CLEN) * DMODEL + d;
    const float* xp = X + xoff;
    const float* dp = g_delta + xoff;
    float* yp = Y + xoff;

    #pragma unroll 2
    for (int t = 0; t < CLEN; t++) {
        float xv = xp[(size_t)t * DMODEL];
        float dt = dp[(size_t)t * DMODEL];
        float dx = dt * xv;
        float bl[16], cl[16];
        const float4* bp = (const float4*)Bsm[t];
        const float4* cp = (const float4*)Csm[t];
        *(float4*)&bl[0]  = bp[0]; *(float4*)&bl[4]  = bp[1];
        *(float4*)&bl[8]  = bp[2]; *(float4*)&bl[12] = bp[3];
        *(float4*)&cl[0]  = cp[0]; *(float4*)&cl[4]  = cp[1];
        *(float4*)&cl[8]  = cp[2]; *(float4*)&cl[12] = cp[3];
        float acc0 = 0.0f, acc1 = 0.0f;
        #pragma unroll
        for (int n = 0; n < 16; n += 2) {
            float a0 = ex2(dt * A2r[n]);
            float a1 = ex2(dt * A2r[n + 1]);
            h[n]     = fmaf(a0, h[n],     dx * bl[n]);
            h[n + 1] = fmaf(a1, h[n + 1], dx * bl[n + 1]);
            acc0 = fmaf(h[n],     cl[n],     acc0);
            acc1 = fmaf(h[n + 1], cl[n + 1], acc1);
        }
        yp[(size_t)t * DMODEL] = acc0 + acc1 + xv * dsk;
    }
}

// ---------------- launch ----------------
extern "C" void kernel_launch(void* const* d_in, const int* in_sizes, int n_in,
                              void* d_out, int out_size)
{
    const float* x     = (const float*)d_in[0];
    const float* A_log = (const float*)d_in[1];
    const float* Dsk   = (const float*)d_in[2];
    const float* Wd    = (const float*)d_in[3];
    const float* bd    = (const float*)d_in[4];
    const float* Wb    = (const float*)d_in[5];
    const float* bb    = (const float*)d_in[6];
    const float* Wc    = (const float*)d_in[7];
    const float* bc    = (const float*)d_in[8];
    float* y = (float*)d_out;

    prep_A2_kernel<<<(DMODEL*NSTATE + 255) / 256, 256>>>(A_log);
    gemm_tf32_softplus<<<dim3(DMODEL / TBN, MROWS / TBM), 256>>>(x, Wd, bd);
    bc_kernel<<<MROWS / 8, 256>>>(x, Wb, bb, Wc, bc);
    scan_phaseA<<<dim3(DMODEL / 256, NCHUNK, B_SZ), 256>>>(x);
    scan_phaseB<<<(B_SZ * DMODEL * NSTATE) / 256, 256>>>();
    scan_phaseC<<<dim3(DMODEL / 256, NCHUNK, B_SZ), 256>>>(x, Dsk, y);
}

// round 5
// speedup vs baseline: 1.8015x; 1.0670x over previous
#include <cuda_runtime.h>
#include <cuda_bf16.h>
#include <math.h>
#include <stdint.h>

// Problem constants
#define B_SZ   4
#define SEQ    2048
#define DMODEL 1024
#define NSTATE 16
#define MROWS  (B_SZ*SEQ)        // 8192
#define NCHUNK 32
#define CLEN   64                // NCHUNK*CLEN == SEQ

// ---------------- device scratch (no allocations allowed) ----------------
__device__ __align__(16) float g_delta[MROWS*DMODEL];           // softplus(x@Wd+bd)
__device__ __align__(16) float g_Bm[MROWS*NSTATE];
__device__ __align__(16) float g_Cm[MROWS*NSTATE];
__device__ __align__(16) float g_A2[DMODEL*NSTATE];             // -exp(A_log)*log2(e)
__device__ __align__(16) float g_P [B_SZ*NCHUNK*DMODEL*NSTATE];
__device__ __align__(16) float g_E [B_SZ*NCHUNK*DMODEL*NSTATE];
__device__ __align__(16) float g_hin[B_SZ*NCHUNK*DMODEL*NSTATE];

// ---------------- helpers ----------------
__device__ __forceinline__ float ex2(float x) {
    float r;
    asm("ex2.approx.ftz.f32 %0, %1;" : "=f"(r) : "f"(x));
    return r;
}
__device__ __forceinline__ float softplus_f(float z) {
    return fmaxf(z, 0.0f) + log1pf(__expf(-fabsf(z)));
}
__device__ __forceinline__ uint32_t to_tf32(float x) {
    uint32_t u;
    asm("cvt.rna.tf32.f32 %0, %1;" : "=r"(u) : "f"(x));
    return u;
}
__device__ __forceinline__ void mma_tf32(
    float& d0, float& d1, float& d2, float& d3,
    uint32_t a0, uint32_t a1, uint32_t a2, uint32_t a3,
    uint32_t b0, uint32_t b1)
{
    asm volatile(
        "mma.sync.aligned.m16n8k8.row.col.f32.tf32.tf32.f32 "
        "{%0,%1,%2,%3}, {%4,%5,%6,%7}, {%8,%9}, {%0,%1,%2,%3};"
        : "+f"(d0), "+f"(d1), "+f"(d2), "+f"(d3)
        : "r"(a0), "r"(a1), "r"(a2), "r"(a3), "r"(b0), "r"(b1));
}
__device__ __forceinline__ uint32_t smem_u32(const void* p) {
    uint32_t a;
    asm("{ .reg .u64 t; cvta.to.shared.u64 t, %1; cvt.u32.u64 %0, t; }"
        : "=r"(a) : "l"(p));
    return a;
}
__device__ __forceinline__ void cp_async16(uint32_t dst, const void* src) {
    asm volatile("cp.async.cg.shared.global [%0], [%1], 16;" :: "r"(dst), "l"(src));
}
#define CP_COMMIT() asm volatile("cp.async.commit_group;" ::: "memory")
#define CP_WAIT(n)  asm volatile("cp.async.wait_group %0;" :: "n"(n) : "memory")

// ---------------- kernel 0: A2 = -exp(A_log) * log2(e) ----------------
__global__ void prep_A2_kernel(const float* __restrict__ A_log) {
    int i = blockIdx.x * 256 + threadIdx.x;
    if (i < DMODEL*NSTATE)
        g_A2[i] = -__expf(A_log[i]) * 1.44269504088896f;
}

// ---------------- kernel 1: delta = softplus(x @ Wd + bd), tf32 mma.sync
// 128x256 block, 8 warps, 64x64 warp tile, cp.async double buffer.
// smem: A [m(128)][k(16)+4pad]  (pad 20 -> 20g+tg covers all 32 banks)
//       B [k(16)][n(256)+4pad]  (pad 260 -> 4tg+g covers all 32 banks)
#define GBM 128
#define GBN 256
#define GBK 16
#define APAD 20
#define BPAD 260
#define AS_WORDS (GBM*APAD)       // 2560
#define BS_WORDS (GBK*BPAD)       // 4160
#define GEMM_SMEM ((2*AS_WORDS + 2*BS_WORDS)*4)   // 53760 bytes

__global__ __launch_bounds__(256, 1) void gemm_tf32_softplus(
    const float* __restrict__ X, const float* __restrict__ W,
    const float* __restrict__ bias)
{
    const int K = DMODEL, N = DMODEL;
    extern __shared__ __align__(16) char smem[];
    float* sA = (float*)smem;                       // [2][GBM][APAD]
    float* sB = (float*)(smem + 2*AS_WORDS*4);      // [2][GBK][BPAD]
    uint32_t sA_u = smem_u32(sA);
    uint32_t sB_u = smem_u32(sB);

    int tid  = threadIdx.x;
    int wid  = tid >> 5, lane = tid & 31;
    int g    = lane >> 2, tg = lane & 3;
    int brow = blockIdx.y * GBM;
    int bcol = blockIdx.x * GBN;

    // global->smem mapping (16B chunks)
    int am0 = tid >> 2, am1 = (tid + 256) >> 2;   // A rows
    int akq = (tid & 3) * 4;                      // A k quad
    int bk0 = tid >> 6, bnq = (tid & 63) * 4;     // B row / col quad
    const float* Ag0 = X + (size_t)(brow + am0) * K + akq;
    const float* Ag1 = X + (size_t)(brow + am1) * K + akq;
    const float* Bg0 = W + (size_t)(bk0     ) * N + bcol + bnq;
    const float* Bg1 = W + (size_t)(bk0 +  4) * N + bcol + bnq;
    const float* Bg2 = W + (size_t)(bk0 +  8) * N + bcol + bnq;
    const float* Bg3 = W + (size_t)(bk0 + 12) * N + bcol + bnq;
    uint32_t dA0 = sA_u + (am0 * APAD + akq) * 4;
    uint32_t dA1 = sA_u + (am1 * APAD + akq) * 4;
    uint32_t dB0 = sB_u + ((bk0     ) * BPAD + bnq) * 4;
    uint32_t dB1 = sB_u + ((bk0 +  4) * BPAD + bnq) * 4;
    uint32_t dB2 = sB_u + ((bk0 +  8) * BPAD + bnq) * 4;
    uint32_t dB3 = sB_u + ((bk0 + 12) * BPAD + bnq) * 4;

    int wm = (wid & 1) * 64;     // warp row offset
    int wn = (wid >> 1) * 64;    // warp col offset

    float acc[4][8][4];
    #pragma unroll
    for (int mf = 0; mf < 4; mf++)
        #pragma unroll
        for (int nf = 0; nf < 8; nf++)
            #pragma unroll
            for (int r = 0; r < 4; r++) acc[mf][nf][r] = 0.0f;

    // prologue: tile 0 into buffer 0
    cp_async16(dA0, Ag0); cp_async16(dA1, Ag1);
    cp_async16(dB0, Bg0); cp_async16(dB1, Bg1);
    cp_async16(dB2, Bg2); cp_async16(dB3, Bg3);
    CP_COMMIT();

    const int NT = K / GBK;   // 64
    int buf = 0;
    #pragma unroll 1
    for (int t = 0; t < NT; t++) {
        if (t + 1 < NT) {
            int k0g = (t + 1) * GBK;
            uint32_t ab = (buf ^ 1) * AS_WORDS * 4;
            uint32_t bb = (buf ^ 1) * BS_WORDS * 4;
            cp_async16(dA0 + ab, Ag0 + k0g);
            cp_async16(dA1 + ab, Ag1 + k0g);
            cp_async16(dB0 + bb, Bg0 + (size_t)k0g * N);
            cp_async16(dB1 + bb, Bg1 + (size_t)k0g * N);
            cp_async16(dB2 + bb, Bg2 + (size_t)k0g * N);
            cp_async16(dB3 + bb, Bg3 + (size_t)k0g * N);
            CP_COMMIT();
            CP_WAIT(1);
        } else {
            CP_WAIT(0);
        }
        __syncthreads();

        const float* cA = sA + buf * AS_WORDS;
        const float* cB = sB + buf * BS_WORDS;
        #pragma unroll
        for (int ks = 0; ks < 2; ks++) {
            int k0 = ks * 8;
            uint32_t af[4][4], bf[8][2];
            #pragma unroll
            for (int mf = 0; mf < 4; mf++) {
                int m0 = wm + mf * 16;
                af[mf][0] = to_tf32(cA[(m0 + g    ) * APAD + k0 + tg    ]);
                af[mf][1] = to_tf32(cA[(m0 + g + 8) * APAD + k0 + tg    ]);
                af[mf][2] = to_tf32(cA[(m0 + g    ) * APAD + k0 + tg + 4]);
                af[mf][3] = to_tf32(cA[(m0 + g + 8) * APAD + k0 + tg + 4]);
            }
            #pragma unroll
            for (int nf = 0; nf < 8; nf++) {
                int n0 = wn + nf * 8;
                bf[nf][0] = to_tf32(cB[(k0 + tg    ) * BPAD + n0 + g]);
                bf[nf][1] = to_tf32(cB[(k0 + tg + 4) * BPAD + n0 + g]);
            }
            #pragma unroll
            for (int mf = 0; mf < 4; mf++)
                #pragma unroll
                for (int nf = 0; nf < 8; nf++)
                    mma_tf32(acc[mf][nf][0], acc[mf][nf][1],
                             acc[mf][nf][2], acc[mf][nf][3],
                             af[mf][0], af[mf][1], af[mf][2], af[mf][3],
                             bf[nf][0], bf[nf][1]);
        }
        __syncthreads();
        buf ^= 1;
    }

    // epilogue: + bias, softplus, store
    #pragma unroll
    for (int nf = 0; nf < 8; nf++) {
        int col = bcol + wn + nf * 8 + tg * 2;
        float bv0 = bias[col], bv1 = bias[col + 1];
        #pragma unroll
        for (int mf = 0; mf < 4; mf++) {
            int row0 = brow + wm + mf * 16 + g;
            float2 o0, o1;
            o0.x = softplus_f(acc[mf][nf][0] + bv0);
            o0.y = softplus_f(acc[mf][nf][1] + bv1);
            o1.x = softplus_f(acc[mf][nf][2] + bv0);
            o1.y = softplus_f(acc[mf][nf][3] + bv1);
            *(float2*)&g_delta[(size_t)row0 * N + col]       = o0;
            *(float2*)&g_delta[(size_t)(row0 + 8) * N + col] = o1;
        }
    }
}

// ---------------- kernel 2: Bm = x@Wb+bb, Cm = x@Wc+bc ----------------
__global__ __launch_bounds__(256) void bc_kernel(
    const float* __restrict__ X,
    const float* __restrict__ Wb, const float* __restrict__ bbv,
    const float* __restrict__ Wc, const float* __restrict__ bcv)
{
    __shared__ __align__(16) float Ws[128][32];
    __shared__ __align__(16) float Xs[8][128];
    int tid  = threadIdx.x;
    int lane = tid & 31;
    int warp = tid >> 5;
    int row0 = blockIdx.x * 8;

    float acc = 0.0f;
    for (int kt = 0; kt < DMODEL; kt += 128) {
        __syncthreads();
        {
            int r  = tid >> 1;
            int hs = tid & 1;
            const float* src = (hs ? Wc : Wb) + (size_t)(kt + r) * NSTATE;
            float4 v0 = ((const float4*)src)[0];
            float4 v1 = ((const float4*)src)[1];
            float4 v2 = ((const float4*)src)[2];
            float4 v3 = ((const float4*)src)[3];
            int cb = hs * 16;
            *(float4*)&Ws[r][cb + 0]  = v0;
            *(float4*)&Ws[r][cb + 4]  = v1;
            *(float4*)&Ws[r][cb + 8]  = v2;
            *(float4*)&Ws[r][cb + 12] = v3;
        }
        {
            int rr = tid >> 5;
            int cc = (tid & 31) * 4;
            *(float4*)&Xs[rr][cc] =
                *(const float4*)(X + (size_t)(row0 + rr) * DMODEL + kt + cc);
        }
        __syncthreads();
        #pragma unroll 8
        for (int kk = 0; kk < 128; kk++)
            acc = fmaf(Xs[warp][kk], Ws[kk][lane], acc);
    }
    acc += (lane < NSTATE) ? bbv[lane] : bcv[lane - NSTATE];
    int row = row0 + warp;
    if (lane < NSTATE) g_Bm[row * NSTATE + lane] = acc;
    else               g_Cm[row * NSTATE + lane - NSTATE] = acc;
}

// ---------------- kernel 3: scan phase A (2 threads per d, 8 states each) --
__global__ __launch_bounds__(256) void scan_phaseA(const float* __restrict__ X)
{
    int tid  = threadIdx.x;
    int d    = blockIdx.x * 128 + (tid >> 1);
    int half = tid & 1;
    int c    = blockIdx.y;
    int b    = blockIdx.z;

    __shared__ __align__(16) float Bsm[CLEN][NSTATE];
    {
        const float4* src = (const float4*)(g_Bm + (size_t)(b * SEQ + c * CLEN) * NSTATE);
        ((float4*)Bsm)[tid] = src[tid];
    }
    float A2r[8];
    {
        const float4* ap = (const float4*)(g_A2 + (size_t)d * NSTATE + half * 8);
        *(float4*)&A2r[0] = ap[0];
        *(float4*)&A2r[4] = ap[1];
    }
    __syncthreads();

    float P[8], E[8];
    #pragma unroll
    for (int n = 0; n < 8; n++) { P[n] = 1.0f; E[n] = 0.0f; }

    size_t xoff = (size_t)(b * SEQ + c * CLEN) * DMODEL + d;
    const float* xp = X + xoff;
    const float* dp = g_delta + xoff;

    #pragma unroll 4
    for (int t = 0; t < CLEN; t++) {
        float xv = xp[(size_t)t * DMODEL];
        float dt = dp[(size_t)t * DMODEL];
        float dx = dt * xv;
        float bl[8];
        const float4* bp = (const float4*)&Bsm[t][half * 8];
        *(float4*)&bl[0] = bp[0];
        *(float4*)&bl[4] = bp[1];
        #pragma unroll
        for (int n = 0; n < 8; n++) {
            float a = ex2(dt * A2r[n]);
            P[n] *= a;
            E[n] = fmaf(a, E[n], dx * bl[n]);
        }
    }

    size_t off = ((size_t)((b * NCHUNK + c) * DMODEL + d)) * NSTATE + half * 8;
    float4* Pp = (float4*)(g_P + off);
    float4* Ep = (float4*)(g_E + off);
    Pp[0] = *(float4*)&P[0];  Pp[1] = *(float4*)&P[4];
    Ep[0] = *(float4*)&E[0];  Ep[1] = *(float4*)&E[4];
}

// ---------------- kernel 4: scan phase B (combine chunks sequentially) ------
__global__ __launch_bounds__(256) void scan_phaseB()
{
    int idx = blockIdx.x * 256 + threadIdx.x;
    int b   = idx >> 14;
    int rem = idx & 16383;
    size_t base = (size_t)b * NCHUNK * DMODEL * NSTATE + rem;
    float h = 0.0f;
    #pragma unroll
    for (int c = 0; c < NCHUNK; c++) {
        size_t off = base + (size_t)c * (DMODEL * NSTATE);
        g_hin[off] = h;
        h = fmaf(g_P[off], h, g_E[off]);
    }
}

// ---------------- kernel 5: scan phase C (2 threads per d, shfl combine) ----
__global__ __launch_bounds__(256) void scan_phaseC(
    const float* __restrict__ X, const float* __restrict__ Dskip,
    float* __restrict__ Y)
{
    int tid  = threadIdx.x;
    int d    = blockIdx.x * 128 + (tid >> 1);
    int half = tid & 1;
    int c    = blockIdx.y;
    int b    = blockIdx.z;

    __shared__ __align__(16) float Bsm[CLEN][NSTATE];
    __shared__ __align__(16) float Csm[CLEN][NSTATE];
    {
        size_t so = (size_t)(b * SEQ + c * CLEN) * NSTATE;
        ((float4*)Bsm)[tid] = ((const float4*)(g_Bm + so))[tid];
        ((float4*)Csm)[tid] = ((const float4*)(g_Cm + so))[tid];
    }
    float A2r[8];
    {
        const float4* ap = (const float4*)(g_A2 + (size_t)d * NSTATE + half * 8);
        *(float4*)&A2r[0] = ap[0];
        *(float4*)&A2r[4] = ap[1];
    }
    float h[8];
    {
        size_t off = ((size_t)((b * NCHUNK + c) * DMODEL + d)) * NSTATE + half * 8;
        const float4* hp = (const float4*)(g_hin + off);
        *(float4*)&h[0] = hp[0];
        *(float4*)&h[4] = hp[1];
    }
    float dsk = Dskip[d];
    __syncthreads();

    size_t xoff = (size_t)(b * SEQ + c * CLEN) * DMODEL + d;
    const float* xp = X + xoff;
    const float* dp = g_delta + xoff;
    float* yp = Y + xoff;

    #pragma unroll 4
    for (int t = 0; t < CLEN; t++) {
        float xv = xp[(size_t)t * DMODEL];
        float dt = dp[(size_t)t * DMODEL];
        float dx = dt * xv;
        float bl[8], cl[8];
        const float4* bp = (const float4*)&Bsm[t][half * 8];
        const float4* cp = (const float4*)&Csm[t][half * 8];
        *(float4*)&bl[0] = bp[0]; *(float4*)&bl[4] = bp[1];
        *(float4*)&cl[0] = cp[0]; *(float4*)&cl[4] = cp[1];
        float acc0 = 0.0f, acc1 = 0.0f;
        #pragma unroll
        for (int n = 0; n < 8; n += 2) {
            float a0 = ex2(dt * A2r[n]);
            float a1 = ex2(dt * A2r[n + 1]);
            h[n]     = fmaf(a0, h[n],     dx * bl[n]);
            h[n + 1] = fmaf(a1, h[n + 1], dx * bl[n + 1]);
            acc0 = fmaf(h[n],     cl[n],     acc0);
            acc1 = fmaf(h[n + 1], cl[n + 1], acc1);
        }
        float acc = acc0 + acc1;
        acc += __shfl_xor_sync(0xFFFFFFFFu, acc, 1);
        if (half == 0)
            yp[(size_t)t * DMODEL] = acc + xv * dsk;
    }
}

// ---------------- launch ----------------
extern "C" void kernel_launch(void* const* d_in, const int* in_sizes, int n_in,
                              void* d_out, int out_size)
{
    const float* x     = (const float*)d_in[0];
    const float* A_log = (const float*)d_in[1];
    const float* Dsk   = (const float*)d_in[2];
    const float* Wd    = (const float*)d_in[3];
    const float* bd    = (const float*)d_in[4];
    const float* Wb    = (const float*)d_in[5];
    const float* bb    = (const float*)d_in[6];
    const float* Wc    = (const float*)d_in[7];
    const float* bc    = (const float*)d_in[8];
    float* y = (float*)d_out;

    static int smem_set = 0;
    if (!smem_set) {
        cudaFuncSetAttribute(gemm_tf32_softplus,
                             cudaFuncAttributeMaxDynamicSharedMemorySize,
                             GEMM_SMEM);
        smem_set = 1;
    }

    prep_A2_kernel<<<(DMODEL*NSTATE + 255) / 256, 256>>>(A_log);
    gemm_tf32_softplus<<<dim3(DMODEL / GBN, MROWS / GBM), 256, GEMM_SMEM>>>(x, Wd, bd);
    bc_kernel<<<MROWS / 8, 256>>>(x, Wb, bb, Wc, bc);
    scan_phaseA<<<dim3(DMODEL / 128, NCHUNK, B_SZ), 256>>>(x);
    scan_phaseB<<<(B_SZ * DMODEL * NSTATE) / 256, 256>>>();
    scan_phaseC<<<dim3(DMODEL / 128, NCHUNK, B_SZ), 256>>>(x, Dsk, y);
}

// round 6
// speedup vs baseline: 2.2742x; 1.2624x over previous
#include <cuda_runtime.h>
#include <cuda_fp16.h>
#include <cuda_bf16.h>
#include <math.h>
#include <stdint.h>

// Problem constants
#define B_SZ   4
#define SEQ    2048
#define DMODEL 1024
#define NSTATE 16
#define MROWS  (B_SZ*SEQ)        // 8192
#define NCHUNK 32
#define CLEN   64                // NCHUNK*CLEN == SEQ

// ---------------- device scratch (no allocations allowed) ----------------
__device__ __align__(16) float g_delta[MROWS*DMODEL];
__device__ __align__(16) float g_Bm[MROWS*NSTATE];
__device__ __align__(16) float g_Cm[MROWS*NSTATE];
__device__ __align__(16) float g_A2[DMODEL*NSTATE];
__device__ __align__(16) float g_P [B_SZ*NCHUNK*DMODEL*NSTATE];
__device__ __align__(16) float g_E [B_SZ*NCHUNK*DMODEL*NSTATE];
__device__ __align__(16) float g_hin[B_SZ*NCHUNK*DMODEL*NSTATE];
__device__ __align__(16) __half g_Xh[MROWS*DMODEL];    // fp16 X      16 MB
__device__ __align__(16) __half g_Wh[DMODEL*DMODEL];   // fp16 Wd     2 MB

// ---------------- helpers ----------------
__device__ __forceinline__ float ex2(float x) {
    float r;
    asm("ex2.approx.ftz.f32 %0, %1;" : "=f"(r) : "f"(x));
    return r;
}
__device__ __forceinline__ float softplus_f(float z) {
    return fmaxf(z, 0.0f) + log1pf(__expf(-fabsf(z)));
}
__device__ __forceinline__ uint32_t smem_u32(const void* p) {
    uint32_t a;
    asm("{ .reg .u64 t; cvta.to.shared.u64 t, %1; cvt.u32.u64 %0, t; }"
        : "=r"(a) : "l"(p));
    return a;
}
__device__ __forceinline__ void cp_async16(uint32_t dst, const void* src) {
    asm volatile("cp.async.cg.shared.global [%0], [%1], 16;" :: "r"(dst), "l"(src));
}
#define CP_COMMIT() asm volatile("cp.async.commit_group;" ::: "memory")
#define CP_WAIT(n)  asm volatile("cp.async.wait_group %0;" :: "n"(n) : "memory")

__device__ __forceinline__ void ldsm_x4(
    uint32_t& r0, uint32_t& r1, uint32_t& r2, uint32_t& r3, uint32_t addr)
{
    asm volatile("ldmatrix.sync.aligned.m8n8.x4.shared.b16 {%0,%1,%2,%3}, [%4];"
                 : "=r"(r0), "=r"(r1), "=r"(r2), "=r"(r3) : "r"(addr));
}
__device__ __forceinline__ void ldsm_x4_t(
    uint32_t& r0, uint32_t& r1, uint32_t& r2, uint32_t& r3, uint32_t addr)
{
    asm volatile("ldmatrix.sync.aligned.m8n8.x4.trans.shared.b16 {%0,%1,%2,%3}, [%4];"
                 : "=r"(r0), "=r"(r1), "=r"(r2), "=r"(r3) : "r"(addr));
}
__device__ __forceinline__ void mma_f16(
    float& d0, float& d1, float& d2, float& d3,
    uint32_t a0, uint32_t a1, uint32_t a2, uint32_t a3,
    uint32_t b0, uint32_t b1)
{
    asm volatile(
        "mma.sync.aligned.m16n8k16.row.col.f32.f16.f16.f32 "
        "{%0,%1,%2,%3}, {%4,%5,%6,%7}, {%8,%9}, {%0,%1,%2,%3};"
        : "+f"(d0), "+f"(d1), "+f"(d2), "+f"(d3)
        : "r"(a0), "r"(a1), "r"(a2), "r"(a3), "r"(b0), "r"(b1));
}

// ---------------- kernel 0: A2 = -exp(A_log) * log2(e) ----------------
__global__ void prep_A2_kernel(const float* __restrict__ A_log) {
    int i = blockIdx.x * 256 + threadIdx.x;
    if (i < DMODEL*NSTATE)
        g_A2[i] = -__expf(A_log[i]) * 1.44269504088896f;
}

// ---------------- conversion: fp32 -> fp16 ----------------
__global__ __launch_bounds__(256) void convert_f16_kernel(
    const float* __restrict__ src, __half* __restrict__ dst)
{
    int i4 = blockIdx.x * 256 + threadIdx.x;     // float4 index
    float4 v = ((const float4*)src)[i4];
    __half2 h0 = __floats2half2_rn(v.x, v.y);
    __half2 h1 = __floats2half2_rn(v.z, v.w);
    ((__half2*)dst)[i4*2]   = h0;
    ((__half2*)dst)[i4*2+1] = h1;
}

// ---------------- kernel 1: delta = softplus(x @ Wd + bd), fp16 mma ------
// 128x256 block, 8 warps, 64x64 warp tile, cp.async double buffer, ldmatrix.
// A smem: [128 m][32 k] half, 64B/row, 4 chunks/row, swz c^=((row>>1)&3)
// B smem: [32 k][256 n] half, 512B/row, 32 chunks/row, swz c^=(k&7)
#define GBM 128
#define GBN 256
#define GBK 32
#define ASZ 8192      // bytes per A buffer
#define BSZ 16384     // bytes per B buffer
#define GEMM_SMEM (2*(ASZ+BSZ))   // 49152

__global__ __launch_bounds__(256, 1) void gemm_f16_softplus(
    const float* __restrict__ bias)
{
    const int K = DMODEL, N = DMODEL;
    extern __shared__ __align__(128) char smem[];
    uint32_t sA_u = smem_u32(smem);              // 2 x 8KB
    uint32_t sB_u = sA_u + 2*ASZ;                // 2 x 16KB

    int tid  = threadIdx.x;
    int wid  = tid >> 5, lane = tid & 31;
    int g    = lane >> 2, tg = lane & 3;
    int brow = blockIdx.y * GBM;
    int bcol = blockIdx.x * GBN;

    // cp.async mappings (16B chunks)
    // A: 512 chunks -> 2/thread. linear ci: row = ci>>2, c = ci&3
    int a_r0 = tid >> 2,          a_c0 = tid & 3;
    int a_r1 = (tid + 256) >> 2,  a_c1 = tid & 3;
    const __half* Ag0 = g_Xh + (size_t)(brow + a_r0) * K + a_c0 * 8;
    const __half* Ag1 = g_Xh + (size_t)(brow + a_r1) * K + a_c1 * 8;
    uint32_t dA0 = (uint32_t)(a_r0 * 64 + (a_c0 ^ ((a_r0 >> 1) & 3)) * 16);
    uint32_t dA1 = (uint32_t)(a_r1 * 64 + (a_c1 ^ ((a_r1 >> 1) & 3)) * 16);
    // B: 1024 chunks -> 4/thread. linear ci: row k = ci>>5, c = ci&31
    int b_r[4], b_c[4];
    uint32_t dB[4];
    const __half* Bg[4];
    #pragma unroll
    for (int j = 0; j < 4; j++) {
        int ci = tid + j * 256;
        b_r[j] = ci >> 5;
        b_c[j] = ci & 31;
        Bg[j]  = g_Wh + (size_t)b_r[j] * N + bcol + b_c[j] * 8;
        dB[j]  = (uint32_t)(b_r[j] * 512 + (b_c[j] ^ (b_r[j] & 7)) * 16);
    }

    int wm = (wid & 1) * 64;
    int wn = (wid >> 1) * 64;

    float acc[4][8][4];
    #pragma unroll
    for (int mf = 0; mf < 4; mf++)
        #pragma unroll
        for (int nf = 0; nf < 8; nf++)
            #pragma unroll
            for (int r = 0; r < 4; r++) acc[mf][nf][r] = 0.0f;

    // precomputed ldmatrix smem offsets (buffer-relative)
    // A: mf tile, ks chunk: row = wm + mf*16 + (lane&15), chunk = ks*2 + (lane>>4)
    uint32_t a_off[4][2];
    #pragma unroll
    for (int mf = 0; mf < 4; mf++)
        #pragma unroll
        for (int ks = 0; ks < 2; ks++) {
            int row = wm + mf * 16 + (lane & 15);
            int c   = ks * 2 + (lane >> 4);
            a_off[mf][ks] = (uint32_t)(row * 64 + (c ^ ((row >> 1) & 3)) * 16);
        }
    // B: nt group (n16), ks: k = ks*16 + (lane&15), chunk = wn/8 + nt*2 + (lane>>4)
    uint32_t b_off[4][2];
    #pragma unroll
    for (int nt = 0; nt < 4; nt++)
        #pragma unroll
        for (int ks = 0; ks < 2; ks++) {
            int k = ks * 16 + (lane & 15);
            int c = (wn >> 3) + nt * 2 + (lane >> 4);
            b_off[nt][ks] = (uint32_t)(k * 512 + (c ^ (k & 7)) * 16);
        }

    // prologue: tile 0 -> buffer 0
    cp_async16(sA_u + dA0, Ag0);
    cp_async16(sA_u + dA1, Ag1);
    #pragma unroll
    for (int j = 0; j < 4; j++) cp_async16(sB_u + dB[j], Bg[j]);
    CP_COMMIT();

    const int NT = K / GBK;   // 32
    int buf = 0;
    #pragma unroll 1
    for (int t = 0; t < NT; t++) {
        if (t + 1 < NT) {
            int k0g = (t + 1) * GBK;
            uint32_t ab = sA_u + (buf ^ 1) * ASZ;
            uint32_t bb = sB_u + (buf ^ 1) * BSZ;
            cp_async16(ab + dA0, Ag0 + k0g);
            cp_async16(ab + dA1, Ag1 + k0g);
            #pragma unroll
            for (int j = 0; j < 4; j++)
                cp_async16(bb + dB[j], Bg[j] + (size_t)k0g * N);
            CP_COMMIT();
            CP_WAIT(1);
        } else {
            CP_WAIT(0);
        }
        __syncthreads();

        uint32_t Ab = sA_u + buf * ASZ;
        uint32_t Bb = sB_u + buf * BSZ;
        #pragma unroll
        for (int ks = 0; ks < 2; ks++) {
            uint32_t af[4][4], bf[4][4];
            #pragma unroll
            for (int mf = 0; mf < 4; mf++)
                ldsm_x4(af[mf][0], af[mf][1], af[mf][2], af[mf][3],
                        Ab + a_off[mf][ks]);
            #pragma unroll
            for (int nt = 0; nt < 4; nt++)
                ldsm_x4_t(bf[nt][0], bf[nt][1], bf[nt][2], bf[nt][3],
                          Bb + b_off[nt][ks]);
            #pragma unroll
            for (int mf = 0; mf < 4; mf++)
                #pragma unroll
                for (int nt = 0; nt < 4; nt++) {
                    mma_f16(acc[mf][2*nt][0],   acc[mf][2*nt][1],
                            acc[mf][2*nt][2],   acc[mf][2*nt][3],
                            af[mf][0], af[mf][1], af[mf][2], af[mf][3],
                            bf[nt][0], bf[nt][1]);
                    mma_f16(acc[mf][2*nt+1][0], acc[mf][2*nt+1][1],
                            acc[mf][2*nt+1][2], acc[mf][2*nt+1][3],
                            af[mf][0], af[mf][1], af[mf][2], af[mf][3],
                            bf[nt][2], bf[nt][3]);
                }
        }
        __syncthreads();
        buf ^= 1;
    }

    // epilogue: + bias, softplus, store
    #pragma unroll
    for (int nf = 0; nf < 8; nf++) {
        int col = bcol + wn + nf * 8 + tg * 2;
        float bv0 = bias[col], bv1 = bias[col + 1];
        #pragma unroll
        for (int mf = 0; mf < 4; mf++) {
            int row0 = brow + wm + mf * 16 + g;
            float2 o0, o1;
            o0.x = softplus_f(acc[mf][nf][0] + bv0);
            o0.y = softplus_f(acc[mf][nf][1] + bv1);
            o1.x = softplus_f(acc[mf][nf][2] + bv0);
            o1.y = softplus_f(acc[mf][nf][3] + bv1);
            *(float2*)&g_delta[(size_t)row0 * N + col]       = o0;
            *(float2*)&g_delta[(size_t)(row0 + 8) * N + col] = o1;
        }
    }
}

// ---------------- kernel 2: Bm = x@Wb+bb, Cm = x@Wc+bc ----------------
__global__ __launch_bounds__(256) void bc_kernel(
    const float* __restrict__ X,
    const float* __restrict__ Wb, const float* __restrict__ bbv,
    const float* __restrict__ Wc, const float* __restrict__ bcv)
{
    __shared__ __align__(16) float Ws[128][32];
    __shared__ __align__(16) float Xs[8][128];
    int tid  = threadIdx.x;
    int lane = tid & 31;
    int warp = tid >> 5;
    int row0 = blockIdx.x * 8;

    float acc = 0.0f;
    for (int kt = 0; kt < DMODEL; kt += 128) {
        __syncthreads();
        {
            int r  = tid >> 1;
            int hs = tid & 1;
            const float* src = (hs ? Wc : Wb) + (size_t)(kt + r) * NSTATE;
            float4 v0 = ((const float4*)src)[0];
            float4 v1 = ((const float4*)src)[1];
            float4 v2 = ((const float4*)src)[2];
            float4 v3 = ((const float4*)src)[3];
            int cb = hs * 16;
            *(float4*)&Ws[r][cb + 0]  = v0;
            *(float4*)&Ws[r][cb + 4]  = v1;
            *(float4*)&Ws[r][cb + 8]  = v2;
            *(float4*)&Ws[r][cb + 12] = v3;
        }
        {
            int rr = tid >> 5;
            int cc = (tid & 31) * 4;
            *(float4*)&Xs[rr][cc] =
                *(const float4*)(X + (size_t)(row0 + rr) * DMODEL + kt + cc);
        }
        __syncthreads();
        #pragma unroll 8
        for (int kk = 0; kk < 128; kk++)
            acc = fmaf(Xs[warp][kk], Ws[kk][lane], acc);
    }
    acc += (lane < NSTATE) ? bbv[lane] : bcv[lane - NSTATE];
    int row = row0 + warp;
    if (lane < NSTATE) g_Bm[row * NSTATE + lane] = acc;
    else               g_Cm[row * NSTATE + lane - NSTATE] = acc;
}

// ---------------- kernel 3: scan phase A (2 threads per d, 8 states each) --
__global__ __launch_bounds__(256) void scan_phaseA(const float* __restrict__ X)
{
    int tid  = threadIdx.x;
    int d    = blockIdx.x * 128 + (tid >> 1);
    int half = tid & 1;
    int c    = blockIdx.y;
    int b    = blockIdx.z;

    __shared__ __align__(16) float Bsm[CLEN][NSTATE];
    {
        const float4* src = (const float4*)(g_Bm + (size_t)(b * SEQ + c * CLEN) * NSTATE);
        ((float4*)Bsm)[tid] = src[tid];
    }
    float A2r[8];
    {
        const float4* ap = (const float4*)(g_A2 + (size_t)d * NSTATE + half * 8);
        *(float4*)&A2r[0] = ap[0];
        *(float4*)&A2r[4] = ap[1];
    }
    __syncthreads();

    float P[8], E[8];
    #pragma unroll
    for (int n = 0; n < 8; n++) { P[n] = 1.0f; E[n] = 0.0f; }

    size_t xoff = (size_t)(b * SEQ + c * CLEN) * DMODEL + d;
    const float* xp = X + xoff;
    const float* dp = g_delta + xoff;

    #pragma unroll 4
    for (int t = 0; t < CLEN; t++) {
        float xv = xp[(size_t)t * DMODEL];
        float dt = dp[(size_t)t * DMODEL];
        float dx = dt * xv;
        float bl[8];
        const float4* bp = (const float4*)&Bsm[t][half * 8];
        *(float4*)&bl[0] = bp[0];
        *(float4*)&bl[4] = bp[1];
        #pragma unroll
        for (int n = 0; n < 8; n++) {
            float a = ex2(dt * A2r[n]);
            P[n] *= a;
            E[n] = fmaf(a, E[n], dx * bl[n]);
        }
    }

    size_t off = ((size_t)((b * NCHUNK + c) * DMODEL + d)) * NSTATE + half * 8;
    float4* Pp = (float4*)(g_P + off);
    float4* Ep = (float4*)(g_E + off);
    Pp[0] = *(float4*)&P[0];  Pp[1] = *(float4*)&P[4];
    Ep[0] = *(float4*)&E[0];  Ep[1] = *(float4*)&E[4];
}

// ---------------- kernel 4: scan phase B ----------------
__global__ __launch_bounds__(256) void scan_phaseB()
{
    int idx = blockIdx.x * 256 + threadIdx.x;
    int b   = idx >> 14;
    int rem = idx & 16383;
    size_t base = (size_t)b * NCHUNK * DMODEL * NSTATE + rem;
    float h = 0.0f;
    #pragma unroll
    for (int c = 0; c < NCHUNK; c++) {
        size_t off = base + (size_t)c * (DMODEL * NSTATE);
        g_hin[off] = h;
        h = fmaf(g_P[off], h, g_E[off]);
    }
}

// ---------------- kernel 5: scan phase C (2 threads per d, shfl combine) ----
__global__ __launch_bounds__(256) void scan_phaseC(
    const float* __restrict__ X, const float* __restrict__ Dskip,
    float* __restrict__ Y)
{
    int tid  = threadIdx.x;
    int d    = blockIdx.x * 128 + (tid >> 1);
    int half = tid & 1;
    int c    = blockIdx.y;
    int b    = blockIdx.z;

    __shared__ __align__(16) float Bsm[CLEN][NSTATE];
    __shared__ __align__(16) float Csm[CLEN][NSTATE];
    {
        size_t so = (size_t)(b * SEQ + c * CLEN) * NSTATE;
        ((float4*)Bsm)[tid] = ((const float4*)(g_Bm + so))[tid];
        ((float4*)Csm)[tid] = ((const float4*)(g_Cm + so))[tid];
    }
    float A2r[8];
    {
        const float4* ap = (const float4*)(g_A2 + (size_t)d * NSTATE + half * 8);
        *(float4*)&A2r[0] = ap[0];
        *(float4*)&A2r[4] = ap[1];
    }
    float h[8];
    {
        size_t off = ((size_t)((b * NCHUNK + c) * DMODEL + d)) * NSTATE + half * 8;
        const float4* hp = (const float4*)(g_hin + off);
        *(float4*)&h[0] = hp[0];
        *(float4*)&h[4] = hp[1];
    }
    float dsk = Dskip[d];
    __syncthreads();

    size_t xoff = (size_t)(b * SEQ + c * CLEN) * DMODEL + d;
    const float* xp = X + xoff;
    const float* dp = g_delta + xoff;
    float* yp = Y + xoff;

    #pragma unroll 4
    for (int t = 0; t < CLEN; t++) {
        float xv = xp[(size_t)t * DMODEL];
        float dt = dp[(size_t)t * DMODEL];
        float dx = dt * xv;
        float bl[8], cl[8];
        const float4* bp = (const float4*)&Bsm[t][half * 8];
        const float4* cp = (const float4*)&Csm[t][half * 8];
        *(float4*)&bl[0] = bp[0]; *(float4*)&bl[4] = bp[1];
        *(float4*)&cl[0] = cp[0]; *(float4*)&cl[4] = cp[1];
        float acc0 = 0.0f, acc1 = 0.0f;
        #pragma unroll
        for (int n = 0; n < 8; n += 2) {
            float a0 = ex2(dt * A2r[n]);
            float a1 = ex2(dt * A2r[n + 1]);
            h[n]     = fmaf(a0, h[n],     dx * bl[n]);
            h[n + 1] = fmaf(a1, h[n + 1], dx * bl[n + 1]);
            acc0 = fmaf(h[n],     cl[n],     acc0);
            acc1 = fmaf(h[n + 1], cl[n + 1], acc1);
        }
        float acc = acc0 + acc1;
        acc += __shfl_xor_sync(0xFFFFFFFFu, acc, 1);
        if (half == 0)
            yp[(size_t)t * DMODEL] = acc + xv * dsk;
    }
}

// ---------------- launch ----------------
extern "C" void kernel_launch(void* const* d_in, const int* in_sizes, int n_in,
                              void* d_out, int out_size)
{
    const float* x     = (const float*)d_in[0];
    const float* A_log = (const float*)d_in[1];
    const float* Dsk   = (const float*)d_in[2];
    const float* Wd    = (const float*)d_in[3];
    const float* bd    = (const float*)d_in[4];
    const float* Wb    = (const float*)d_in[5];
    const float* bb    = (const float*)d_in[6];
    const float* Wc    = (const float*)d_in[7];
    const float* bc    = (const float*)d_in[8];
    float* y = (float*)d_out;

    __half* xh_sym = nullptr;
    __half* wh_sym = nullptr;
    cudaGetSymbolAddress((void**)&xh_sym, g_Xh);
    cudaGetSymbolAddress((void**)&wh_sym, g_Wh);
    cudaFuncSetAttribute(gemm_f16_softplus,
                         cudaFuncAttributeMaxDynamicSharedMemorySize,
                         GEMM_SMEM);

    prep_A2_kernel<<<(DMODEL*NSTATE + 255) / 256, 256>>>(A_log);
    convert_f16_kernel<<<(MROWS * DMODEL / 4) / 256, 256>>>(x, xh_sym);
    convert_f16_kernel<<<(DMODEL * DMODEL / 4) / 256, 256>>>(Wd, wh_sym);
    gemm_f16_softplus<<<dim3(DMODEL / GBN, MROWS / GBM), 256, GEMM_SMEM>>>(bd);
    bc_kernel<<<MROWS / 8, 256>>>(x, Wb, bb, Wc, bc);
    scan_phaseA<<<dim3(DMODEL / 128, NCHUNK, B_SZ), 256>>>(x);
    scan_phaseB<<<(B_SZ * DMODEL * NSTATE) / 256, 256>>>();
    scan_phaseC<<<dim3(DMODEL / 128, NCHUNK, B_SZ), 256>>>(x, Dsk, y);
}